// round 1
// baseline (speedup 1.0000x reference)
#include <cuda_runtime.h>
#include <cuda_bf16.h>

typedef unsigned long long ull;

// Precomputed interleaved weight pairs: wp[s_in][dh1][dw1][dh2][dw2][s_out] = (k[d], k_transposed[d])
__device__ ull g_wp[1296];

__device__ __forceinline__ ull pack2(float x, float y) {
    ull r; asm("mov.b64 %0, {%1, %2};" : "=l"(r) : "f"(x), "f"(y)); return r;
}
__device__ __forceinline__ ull fma2(ull a, ull b, ull c) {
    ull d; asm("fma.rn.f32x2 %0, %1, %2, %3;" : "=l"(d) : "l"(a), "l"(b), "l"(c)); return d;
}
__device__ __forceinline__ float2 unpack2(ull v) {
    float2 f; asm("mov.b64 {%0, %1}, %2;" : "=f"(f.x), "=f"(f.y) : "l"(v)); return f;
}

// ---------------------------------------------------------------------------
// Prep: build 1296 weight pairs.
// Index i = ((((s_in*3 + dh1)*3 + dw1)*3 + dh2)*3 + dw2)*4 + s_out
// ds1 = s1i - s1o + 1, ds2 = s2i - s2o + 1 (always in [0,2] since s dims are size 2)
// k index (C-order over (ds1,ds2,dh1,dw1,dh2,dw2), each 0..2)
// transposed kernel: k'[ds1,ds2,dh1,dw1,dh2,dw2] = k[ds2,ds1,dh2,dw2,dh1,dw1]
// ---------------------------------------------------------------------------
__global__ void prep_kernel(const float* __restrict__ kern) {
    int i = blockIdx.x * blockDim.x + threadIdx.x;
    if (i >= 1296) return;
    int so   = i & 3;
    int dw2  = (i >> 2) % 3;
    int dh2  = (i / 12) % 3;
    int dw1  = (i / 36) % 3;
    int dh1  = (i / 108) % 3;
    int s_in = i / 324;
    int s1i = s_in >> 1, s2i = s_in & 1;
    int s1o = so >> 1,   s2o = so & 1;
    int ds1 = s1i - s1o + 1;
    int ds2 = s2i - s2o + 1;
    float wk  = kern[((((ds1*3 + ds2)*3 + dh1)*3 + dw1)*3 + dh2)*3 + dw2];
    float wkt = kern[((((ds2*3 + ds1)*3 + dh2)*3 + dw2)*3 + dh1)*3 + dw1];
    g_wp[i] = pack2(wk, wkt);
}

// ---------------------------------------------------------------------------
// Main conv kernel.
// Output tile per block: (h1,w1,h2,w2) = (4,4,8,8) = 1024 points, 256 threads,
// each thread computes 4 consecutive w2 points.
// Shared: 4 relu'd input halo planes [6][6][10][12-padded] + 1296 weight pairs.
// ---------------------------------------------------------------------------
#define PLANE_F   4320            // 6*6*10*12 floats
#define SMEM_F    (4 * PLANE_F)   // 17280 floats
#define SMEM_BYTES (SMEM_F * 4 + 1296 * 8)   // 69120 + 10368 = 79488

__global__ __launch_bounds__(256, 2)
void conv_kernel(const float* __restrict__ x, float* __restrict__ out) {
    extern __shared__ float sm[];
    ull* ws = (ull*)(sm + SMEM_F);

    const int tid = threadIdx.x;
    const int bid = blockIdx.x;
    const int bw2 = bid & 3;          // w2 tile (of 8)
    const int bh2 = (bid >> 2) & 3;   // h2 tile (of 8)
    const int bw1 = (bid >> 4) & 7;   // w1 tile (of 4)
    const int bh1 = bid >> 7;         // h1 tile (of 4)

    const int H1o = bh1 * 4 - 1, W1o = bw1 * 4 - 1;
    const int H2o = bh2 * 8 - 1, W2o = bw2 * 8 - 1;

    // Load all 4 (s1,s2) halo planes, relu'd, zero-padded at boundaries.
    for (int i = tid; i < 4 * 3600; i += 256) {
        int a4 = i % 10; int t = i / 10;
        int a3 = t % 10; t /= 10;
        int a2 = t % 6;  t /= 6;
        int a1 = t % 6;  int s = t / 6;
        int g1 = H1o + a1, g2 = W1o + a2, g3 = H2o + a3, g4 = W2o + a4;
        float v = 0.0f;
        if (((unsigned)g1 < 32u) && ((unsigned)g2 < 32u) &&
            ((unsigned)g3 < 32u) && ((unsigned)g4 < 32u)) {
            v = fmaxf(x[(((s * 32 + g1) * 32 + g2) * 32 + g3) * 32 + g4], 0.0f);
        }
        sm[s * PLANE_F + ((a1 * 6 + a2) * 10 + a3) * 12 + a4] = v;
    }
    for (int i = tid; i < 1296; i += 256) ws[i] = g_wp[i];
    __syncthreads();

    // Thread -> output coords within tile
    const int w2b = (tid & 1) * 4;       // 0 or 4; thread owns w2b..w2b+3
    const int h2  = (tid >> 1) & 7;
    const int w1  = (tid >> 4) & 3;
    const int h1  = tid >> 6;

    // acc[p][s_out] = (acc_k, acc_k') packed
    ull acc[4][4];
#pragma unroll
    for (int p = 0; p < 4; p++)
#pragma unroll
        for (int so = 0; so < 4; so++) acc[p][so] = 0ull;

#pragma unroll 1
    for (int s_in = 0; s_in < 4; s_in++) {
        const float* pl = sm + s_in * PLANE_F;
#pragma unroll 1
        for (int dh1 = 0; dh1 < 3; dh1++) {
#pragma unroll
            for (int dw1 = 0; dw1 < 3; dw1++) {
#pragma unroll
                for (int dh2 = 0; dh2 < 3; dh2++) {
                    const float* row = pl +
                        (((h1 + dh1) * 6 + (w1 + dw1)) * 10 + (h2 + dh2)) * 12 + w2b;
                    // 6 contiguous, 16B-aligned input floats
                    float4 v4 = *(const float4*)row;
                    float2 v2 = *(const float2*)(row + 4);
                    ull xp[6];
                    xp[0] = pack2(v4.x, v4.x);
                    xp[1] = pack2(v4.y, v4.y);
                    xp[2] = pack2(v4.z, v4.z);
                    xp[3] = pack2(v4.w, v4.w);
                    xp[4] = pack2(v2.x, v2.x);
                    xp[5] = pack2(v2.y, v2.y);
                    const ull* wrow = ws + (((s_in * 3 + dh1) * 3 + dw1) * 3 + dh2) * 12;
#pragma unroll
                    for (int dw2 = 0; dw2 < 3; dw2++) {
#pragma unroll
                        for (int so = 0; so < 4; so++) {
                            ull w = wrow[dw2 * 4 + so];
#pragma unroll
                            for (int p = 0; p < 4; p++) {
                                acc[p][so] = fma2(xp[dw2 + p], w, acc[p][so]);
                            }
                        }
                    }
                }
            }
        }
    }

    // Epilogue: sigmoid both branches, mask by (x != 0), sum over the 4 s_out
    const int H1 = bh1 * 4 + h1, W1 = bw1 * 4 + w1;
    const int H2 = bh2 * 8 + h2, W2 = bw2 * 8 + w2b;
    const int base_sp = (((H1 * 32 + W1) * 32 + H2) * 32) + W2;

    float res[4];
#pragma unroll
    for (int p = 0; p < 4; p++) {
        float sum = 0.0f;
#pragma unroll
        for (int so = 0; so < 4; so++) {
            float2 a = unpack2(acc[p][so]);
            float xs = x[so * 1048576 + base_sp + p];
            float s1 = 1.0f / (1.0f + __expf(-a.x));
            float s2 = 1.0f / (1.0f + __expf(-a.y));
            sum += (xs != 0.0f) ? (s1 + s2) : 0.0f;
        }
        res[p] = sum;
    }
    float4 r4 = make_float4(res[0], res[1], res[2], res[3]);
    *(float4*)(out + base_sp) = r4;
}

extern "C" void kernel_launch(void* const* d_in, const int* in_sizes, int n_in,
                              void* d_out, int out_size) {
    const float* x    = (const float*)d_in[0];   // (1,2,2,32,32,32,32)
    const float* kern = (const float*)d_in[1];   // (729,)
    float* out = (float*)d_out;                  // (1,32,32,32,32)

    prep_kernel<<<6, 256>>>(kern);

    cudaFuncSetAttribute(conv_kernel,
                         cudaFuncAttributeMaxDynamicSharedMemorySize, SMEM_BYTES);
    conv_kernel<<<1024, 256, SMEM_BYTES>>>(x, out);
}